// round 15
// baseline (speedup 1.0000x reference)
#include <cuda_runtime.h>
#include <cuda_bf16.h>
#include <math.h>
#include <cstdint>

#define NB 64
#define NN 300
#define NH 64
#define ROWS (NB*NN)        /* 19200 */
#define HC2  4096           /* HC*HC */
#define SP   320            /* padded contraction dim for S / H^T */

typedef unsigned long long ull;

// ---------------- scratch (device globals; .bss => zero-initialized) --------
__device__ float g_Hm  [NN*HC2];        // H node-major fp32 [n][b*64+c] (feeds HT)
__device__ float g_A   [NN*NN];         // supports fp32     [n][m]
__device__ float g_bn  [NN*NH];         // per-node bias     [n][o]
__device__ __align__(16) __nv_bfloat16 g_XGh[NN*12288]; // XG hi [n][b*192+j]
__device__ __align__(16) __nv_bfloat16 g_XGl[NN*12288]; // XG lo
__device__ __align__(16) __nv_bfloat16 g_Wnh[NN*12288]; // Wn hi [n][j*64+o]
__device__ __align__(16) __nv_bfloat16 g_Wnl[NN*12288]; // Wn lo
__device__ __align__(16) __nv_bfloat16 g_H2h[ROWS*NH];  // H2 hi [row][i]
__device__ __align__(16) __nv_bfloat16 g_H2l[ROWS*NH];  // H2 lo
__device__ __align__(16) __nv_bfloat16 g_Wh [HC2*NH];   // W_out hi (native [c][i])
__device__ __align__(16) __nv_bfloat16 g_Wl [HC2*NH];   // W_out lo
__device__ __align__(16) __nv_bfloat16 g_Sh [2*384*SP]; // S_k hi [k][n][m]
__device__ __align__(16) __nv_bfloat16 g_Sl [2*384*SP]; // S_k lo
__device__ __align__(16) __nv_bfloat16 g_HTh[HC2*SP];   // H^T hi [col][m]
__device__ __align__(16) __nv_bfloat16 g_HTl[HC2*SP];   // H^T lo

// tanh = 1 - 2/(e^{2x}+1): 3 FMA-pipe ops + 2 MUFU, no clamp needed.
__device__ __forceinline__ float my_tanh(float x) {
    float e = __expf(2.f * x);
    float q = __fdividef(2.f, e + 1.f);
    return 1.f - q;
}

// ---------------- stable-PTX tensor helpers ---------------------------------
__device__ __forceinline__ uint32_t smem_u32(const void* p) {
    uint32_t a;
    asm("{ .reg .u64 t; cvta.to.shared.u64 t, %1; cvt.u32.u64 %0, t; }"
        : "=r"(a) : "l"(p));
    return a;
}
__device__ __forceinline__ void ldm4(uint32_t* r, uint32_t addr) {
    asm volatile("ldmatrix.sync.aligned.m8n8.x4.shared.b16 {%0,%1,%2,%3}, [%4];"
                 : "=r"(r[0]), "=r"(r[1]), "=r"(r[2]), "=r"(r[3]) : "r"(addr));
}
__device__ __forceinline__ void ldm2(uint32_t* r, uint32_t addr) {
    asm volatile("ldmatrix.sync.aligned.m8n8.x2.shared.b16 {%0,%1}, [%2];"
                 : "=r"(r[0]), "=r"(r[1]) : "r"(addr));
}
__device__ __forceinline__ void ldm2t(uint32_t* r, uint32_t addr) {
    asm volatile("ldmatrix.sync.aligned.m8n8.x2.trans.shared.b16 {%0,%1}, [%2];"
                 : "=r"(r[0]), "=r"(r[1]) : "r"(addr));
}
__device__ __forceinline__ void mma_bf16(float* c, const uint32_t* a,
                                         const uint32_t* b) {
    asm volatile(
        "mma.sync.aligned.m16n8k16.row.col.f32.bf16.bf16.f32 "
        "{%0,%1,%2,%3}, {%4,%5,%6,%7}, {%8,%9}, {%0,%1,%2,%3};"
        : "+f"(c[0]), "+f"(c[1]), "+f"(c[2]), "+f"(c[3])
        : "r"(a[0]), "r"(a[1]), "r"(a[2]), "r"(a[3]), "r"(b[0]), "r"(b[1]));
}
__device__ __forceinline__ void cp16(uint32_t smem, const void* g) {
    asm volatile("cp.async.cg.shared.global [%0], [%1], 16;"
                 :: "r"(smem), "l"(__cvta_generic_to_global(g)));
}
__device__ __forceinline__ void cp_commit() {
    asm volatile("cp.async.commit_group;" ::: "memory");
}
__device__ __forceinline__ void cp_wait0() {
    asm volatile("cp.async.wait_group 0;" ::: "memory");
}
__device__ __forceinline__ void cp_wait1() {
    asm volatile("cp.async.wait_group 1;" ::: "memory");
}
__device__ __forceinline__ void bf16_split(float v, __nv_bfloat16& h,
                                           __nv_bfloat16& l) {
    h = __float2bfloat16(v);
    l = __float2bfloat16(v - __bfloat162float(h));
}

// ---------------- L1: all independent prologue work in one grid -------------
__global__ void __launch_bounds__(320) L1_prologue(
        const float* __restrict__ z,
        const float* __restrict__ W_in,
        const float* __restrict__ b_in,
        const float* __restrict__ W_out,
        const float* __restrict__ node_emb,
        const float* __restrict__ wpool,
        const float* __restrict__ bpool) {
    __shared__ float buf[8320];
    int t = threadIdx.x;
    int blk = blockIdx.x;
    if (blk < 300) {
        float* Wt = buf;            // [64][64]  Wt[i][o] = W_in[o][i]
        float* zs = buf + 4096;     // 64 rows of z
        int rowBase = blk * 64;
        for (int idx = t; idx < 4096; idx += 320) {
            int o = idx >> 6, i = idx & 63;
            Wt[i*64 + o] = W_in[idx];
        }
        for (int idx4 = t; idx4 < 1024; idx4 += 320)
            *(float4*)(zs + idx4*4) = *(const float4*)(z + (size_t)rowBase*64 + idx4*4);
        __syncthreads();

        if (t < 256) {
            int o = t & 63, rg = t >> 6;
            float acc[16];
            float bo = b_in[o];
            #pragma unroll
            for (int r = 0; r < 16; r++) acc[r] = bo;
            const float* zrow = zs + rg*16*64;
            #pragma unroll 4
            for (int i = 0; i < 64; i++) {
                float w = Wt[i*64 + o];
                #pragma unroll
                for (int r = 0; r < 16; r++)
                    acc[r] = fmaf(zrow[r*64 + i], w, acc[r]);
            }
            #pragma unroll
            for (int r = 0; r < 16; r++) {
                float h = fmaxf(acc[r], 0.f);
                int row = rowBase + rg*16 + r;
                int b = row / NN, n = row - b*NN;
                g_Hm[(size_t)n*HC2 + b*64 + o] = h;
                __nv_bfloat16 hh, hl;
                bf16_split(h, hh, hl);
                size_t dst = (size_t)n*12288 + b*192 + o;   // XG plane 0
                g_XGh[dst] = hh;
                g_XGl[dst] = hl;
            }
        }
    } else if (blk < 332) {
        size_t base = (size_t)(blk - 300) * 8192;
        for (int idx = t; idx < 8192; idx += 320) {
            float wv = W_out[base + idx];
            __nv_bfloat16 h, l;
            bf16_split(wv, h, l);
            g_Wh[base + idx] = h;
            g_Wl[base + idx] = l;
        }
    } else if (blk < 632) {
        int n = blk - 332;
        float* E   = buf;
        float* red = buf + 3000;
        for (int idx = t; idx < NN*10; idx += 320) E[idx] = node_emb[idx];
        if (t < 192) red[320 + t] = -1e30f;
        __syncthreads();

        float v = 0.f;
        if (t < NN) {
            float dot = 0.f;
            #pragma unroll
            for (int d = 0; d < 10; d++) dot = fmaf(E[n*10+d], E[t*10+d], dot);
            v = fmaxf(dot, 0.f);
        }
        red[t] = (t < NN) ? v : -1e30f;
        __syncthreads();
        #pragma unroll
        for (int s = 256; s > 0; s >>= 1) {
            if (t < s) red[t] = fmaxf(red[t], red[t+s]);
            __syncthreads();
        }
        float mx = red[0];
        __syncthreads();

        float ev = (t < NN) ? __expf(v - mx) : 0.f;
        red[t] = ev;
        if (t < 192) red[320 + t] = 0.f;
        __syncthreads();
        #pragma unroll
        for (int s = 256; s > 0; s >>= 1) {
            if (t < s) red[t] += red[t+s];
            __syncthreads();
        }
        float inv = 1.f / red[0];
        if (t < NN) {
            float a = ev * inv;
            g_A[n*NN + t] = a;
            __nv_bfloat16 h, l;
            bf16_split(a, h, l);
            g_Sh[n*SP + t] = h;
            g_Sl[n*SP + t] = l;
        }
    } else if (blk < 728) {
        int jt = (blk - 632) * 128;
        float* E   = buf;
        float* wps = buf + 3000;
        for (int idx = t; idx < NN*10; idx += 320) E[idx] = node_emb[idx];
        for (int idx = t; idx < 1280; idx += 320) {
            int d = idx >> 7, jj = idx & 127;
            wps[idx] = wpool[(size_t)d*12288 + jt + jj];
        }
        __syncthreads();
        if (t < 256) {
            int jj = t & 127, half = t >> 7;
            const float* w0 = wps + jj;
            for (int n = half; n < NN; n += 2) {
                float acc = 0.f;
                const float* en = E + n*10;
                #pragma unroll
                for (int d = 0; d < 10; d++)
                    acc = fmaf(en[d], w0[d*128], acc);
                __nv_bfloat16 h, l;
                bf16_split(acc, h, l);
                size_t dst = (size_t)n*12288 + jt + jj;
                g_Wnh[dst] = h;
                g_Wnl[dst] = l;
            }
        }
    } else {
        float* E   = buf;
        float* wps = buf + 3000;
        for (int idx = t; idx < 640; idx += 320) wps[idx] = bpool[idx];
        for (int idx = t; idx < NN*10; idx += 320) E[idx] = node_emb[idx];
        __syncthreads();
        for (int idx = t; idx < NN*64; idx += 320) {
            int n = idx >> 6, o = idx & 63;
            float acc = 0.f;
            #pragma unroll
            for (int d = 0; d < 10; d++)
                acc = fmaf(E[n*10+d], wps[d*64 + o], acc);
            g_bn[idx] = acc;
        }
    }
}

// ---------------- L2: Chebyshev (0..299) + H transpose/split (300..363) -----
__global__ void __launch_bounds__(320) L2_cheb_ht() {
    __shared__ float buf[4160];
    int t = threadIdx.x;
    int blk = blockIdx.x;
    if (blk < 300) {
        int n = blk;
        float* arow = buf;
        for (int idx = t; idx < NN; idx += 320) arow[idx] = g_A[n*NN + idx];
        __syncthreads();
        if (t < NN) {
            float acc = 0.f;
            #pragma unroll 4
            for (int p = 0; p < NN; p++)
                acc = fmaf(arow[p], g_A[p*NN + t], acc);
            float v = 2.f*acc - ((t == n) ? 1.f : 0.f);
            __nv_bfloat16 h, l;
            bf16_split(v, h, l);
            g_Sh[384*SP + n*SP + t] = h;
            g_Sl[384*SP + n*SP + t] = l;
        }
    } else {
        float* Ts = buf;            // [64][65]
        int cb = (blk - 300) * 64;
        for (int m0 = 0; m0 < NN; m0 += 64) {
            int mc = min(64, NN - m0);
            __syncthreads();
            for (int idx = t; idx < 4096; idx += 320) {
                int mm = idx >> 6, c = idx & 63;
                if (mm < mc)
                    Ts[mm*65 + c] = g_Hm[(size_t)(m0+mm)*HC2 + cb + c];
            }
            __syncthreads();
            for (int idx = t; idx < 4096; idx += 320) {
                int c = idx >> 6, mm = idx & 63;
                if (mm < mc) {
                    __nv_bfloat16 h, l;
                    bf16_split(Ts[mm*65 + c], h, l);
                    g_HTh[(size_t)(cb+c)*SP + m0 + mm] = h;
                    g_HTl[(size_t)(cb+c)*SP + m0 + mm] = l;
                }
            }
        }
    }
}

// ---------------- K4: XG_k = S_k @ Hm via mma.sync; 96-row tiles ------------
__global__ void __launch_bounds__(256, 2) k4_mma() {
    extern __shared__ char smem[];
    uint32_t sb = smem_u32(smem);
    int t = threadIdx.x, w = t >> 5, lane = t & 31;
    int rowBase = blockIdx.x * 96;
    int colBase = blockIdx.y * 128;
    int kz = blockIdx.z;
    const __nv_bfloat16* Sh = g_Sh + (size_t)kz*384*SP;
    const __nv_bfloat16* Sl = g_Sl + (size_t)kz*384*SP;
    int wm = (w & 1) * 48, wn = (w >> 1) * 32;

    int g4 = lane >> 3;
    int rsel = (g4 & 1) * 8 + (lane & 7);
    int kselA = (g4 >> 1) * 8;
    int nsel = lane & 7;
    int kselB = ((lane >> 3) & 1) * 8;
    uint32_t aOff[3], bOff[4];
    #pragma unroll
    for (int mt = 0; mt < 3; mt++)
        aOff[mt] = (uint32_t)((wm + mt*16 + rsel)*80 + kselA*2);
    #pragma unroll
    for (int nt = 0; nt < 4; nt++)
        bOff[nt] = (uint32_t)((wn + nt*8 + nsel)*80 + kselB*2);

    float acc[3][4][4];
    #pragma unroll
    for (int mt = 0; mt < 3; mt++)
        #pragma unroll
        for (int nt = 0; nt < 4; nt++)
            #pragma unroll
            for (int q = 0; q < 4; q++) acc[mt][nt][q] = 0.f;

    const int NC = 10;
    for (int idx = t; idx < 768; idx += 256) {
        int arr = idx / 384, rem = idx % 384;
        int r = rem >> 2, c4 = rem & 3;
        cp16(sb + arr*7680 + r*80 + c4*16,
             (arr ? Sl : Sh) + (size_t)(rowBase + r)*SP + c4*8);
    }
    for (int idx = t; idx < 1024; idx += 256) {
        int arr = idx >> 9, rem = idx & 511;
        int r = rem >> 2, c4 = rem & 3;
        cp16(sb + 30720 + arr*10240 + r*80 + c4*16,
             (arr ? g_HTl : g_HTh) + (size_t)(colBase + r)*SP + c4*8);
    }
    cp_commit();

    for (int c = 0; c < NC; c++) {
        int stage = c & 1;
        if (c + 1 < NC) {
            int m0 = (c + 1) * 32, ns = (c + 1) & 1;
            for (int idx = t; idx < 768; idx += 256) {
                int arr = idx / 384, rem = idx % 384;
                int r = rem >> 2, c4 = rem & 3;
                cp16(sb + ns*15360 + arr*7680 + r*80 + c4*16,
                     (arr ? Sl : Sh) + (size_t)(rowBase + r)*SP + m0 + c4*8);
            }
            for (int idx = t; idx < 1024; idx += 256) {
                int arr = idx >> 9, rem = idx & 511;
                int r = rem >> 2, c4 = rem & 3;
                cp16(sb + 30720 + ns*20480 + arr*10240 + r*80 + c4*16,
                     (arr ? g_HTl : g_HTh) + (size_t)(colBase + r)*SP + m0 + c4*8);
            }
            cp_commit();
            cp_wait1();
        } else {
            cp_wait0();
        }
        __syncthreads();

        uint32_t sA = sb + stage*15360;
        uint32_t sB = sb + 30720 + stage*20480;
        #pragma unroll
        for (int ks = 0; ks < 2; ks++) {
            uint32_t ah[3][4], al[3][4], bh[4][2], bl[4][2];
            #pragma unroll
            for (int mt = 0; mt < 3; mt++) {
                ldm4(ah[mt], sA + aOff[mt] + ks*32);
                ldm4(al[mt], sA + 7680 + aOff[mt] + ks*32);
            }
            #pragma unroll
            for (int nt = 0; nt < 4; nt++) {
                ldm2(bh[nt], sB + bOff[nt] + ks*32);
                ldm2(bl[nt], sB + 10240 + bOff[nt] + ks*32);
            }
            #pragma unroll
            for (int mt = 0; mt < 3; mt++)
                #pragma unroll
                for (int nt = 0; nt < 4; nt++) {
                    mma_bf16(acc[mt][nt], ah[mt], bh[nt]);
                    mma_bf16(acc[mt][nt], ah[mt], bl[nt]);
                    mma_bf16(acc[mt][nt], al[mt], bh[nt]);
                }
        }
        __syncthreads();
    }

    int plane = (kz + 1) * 64;
    #pragma unroll
    for (int nt = 0; nt < 4; nt++) {
        int col = colBase + wn + nt*8 + (lane & 3)*2;
        int b = col >> 6, cc = col & 63;
        size_t boff = (size_t)b*192 + plane + cc;
        #pragma unroll
        for (int mt = 0; mt < 3; mt++) {
            int n0 = rowBase + wm + mt*16 + (lane >> 2);
            if (n0 < NN) {
                __nv_bfloat16 h0, l0, h1, l1;
                bf16_split(acc[mt][nt][0], h0, l0);
                bf16_split(acc[mt][nt][1], h1, l1);
                *(__nv_bfloat162*)(g_XGh + (size_t)n0*12288 + boff) = __halves2bfloat162(h0, h1);
                *(__nv_bfloat162*)(g_XGl + (size_t)n0*12288 + boff) = __halves2bfloat162(l0, l1);
            }
            if (n0 + 8 < NN) {
                __nv_bfloat16 h0, l0, h1, l1;
                bf16_split(acc[mt][nt][2], h0, l0);
                bf16_split(acc[mt][nt][3], h1, l1);
                *(__nv_bfloat162*)(g_XGh + (size_t)(n0+8)*12288 + boff) = __halves2bfloat162(h0, h1);
                *(__nv_bfloat162*)(g_XGl + (size_t)(n0+8)*12288 + boff) = __halves2bfloat162(l0, l1);
            }
        }
    }
}

// ---------------- K5: per-node [64,192]@[192,64] via mma.sync (R13 shape) ---
#define K5_AL 25600
#define K5_BH 51200
#define K5_BL 78848
__global__ void __launch_bounds__(256, 2) k5_mma() {
    extern __shared__ char smem[];
    uint32_t sb = smem_u32(smem);
    int t = threadIdx.x, w = t >> 5, lane = t & 31;
    int n = blockIdx.x;

    const __nv_bfloat16* Ah = g_XGh + (size_t)n*12288;
    const __nv_bfloat16* Al = g_XGl + (size_t)n*12288;
    const __nv_bfloat16* Bh = g_Wnh + (size_t)n*12288;
    const __nv_bfloat16* Bl = g_Wnl + (size_t)n*12288;

    for (int idx = t; idx < 1536; idx += 256) {       // A: 64 rows x 24 chunks
        int r = idx / 24, cc = idx - r*24;
        cp16(sb + r*400 + cc*16,          Ah + r*192 + cc*8);
        cp16(sb + K5_AL + r*400 + cc*16,  Al + r*192 + cc*8);
    }
    for (int idx = t; idx < 1536; idx += 256) {       // B: 192 rows x 8 chunks
        int r = idx >> 3, cc = idx & 7;
        cp16(sb + K5_BH + r*144 + cc*16,  Bh + r*64 + cc*8);
        cp16(sb + K5_BL + r*144 + cc*16,  Bl + r*64 + cc*8);
    }
    cp_commit();
    cp_wait0();
    __syncthreads();

    int wm = (w & 3) * 16, wn = (w >> 2) * 32;
    int g4 = lane >> 3;
    int rsel = (g4 & 1) * 8 + (lane & 7);
    int kselA = (g4 >> 1) * 8;
    uint32_t aAddrH = sb + (uint32_t)((wm + rsel)*400 + kselA*2);
    uint32_t aAddrL = aAddrH + K5_AL;
    uint32_t bRow = (uint32_t)(lane & 15);
    uint32_t bAddr[4];
    #pragma unroll
    for (int nt = 0; nt < 4; nt++)
        bAddr[nt] = sb + K5_BH + bRow*144 + (uint32_t)((wn + nt*8)*2);

    float acc[4][4];
    #pragma unroll
    for (int nt = 0; nt < 4; nt++)
        #pragma unroll
        for (int q = 0; q < 4; q++) acc[nt][q] = 0.f;

    #pragma unroll
    for (int kc = 0; kc < 12; kc++) {
        uint32_t ah[4], al[4];
        ldm4(ah, aAddrH + kc*32);
        ldm4(al, aAddrL + kc*32);
        #pragma unroll
        for (int nt = 0; nt < 4; nt++) {
            uint32_t bh[2], bl[2];
            ldm2t(bh, bAddr[nt] + (uint32_t)(kc*16*144));
            ldm2t(bl, bAddr[nt] + (uint32_t)(K5_BL - K5_BH) + (uint32_t)(kc*16*144));
            mma_bf16(acc[nt], ah, bh);
            mma_bf16(acc[nt], ah, bl);
            mma_bf16(acc[nt], al, bh);
        }
    }

    #pragma unroll
    for (int nt = 0; nt < 4; nt++) {
        int o = wn + nt*8 + (lane & 3)*2;
        float2 bv = *(const float2*)(g_bn + n*64 + o);
        int b0 = wm + (lane >> 2);
        float v0 = acc[nt][0] + bv.x, v1 = acc[nt][1] + bv.y;
        float v2 = acc[nt][2] + bv.x, v3 = acc[nt][3] + bv.y;
        __nv_bfloat16 h0, l0, h1, l1, h2, l2, h3, l3;
        bf16_split(v0, h0, l0); bf16_split(v1, h1, l1);
        bf16_split(v2, h2, l2); bf16_split(v3, h3, l3);
        size_t r0 = ((size_t)(b0*NN + n))*64 + o;
        size_t r1 = ((size_t)((b0+8)*NN + n))*64 + o;
        *(__nv_bfloat162*)(g_H2h + r0) = __halves2bfloat162(h0, h1);
        *(__nv_bfloat162*)(g_H2l + r0) = __halves2bfloat162(l0, l1);
        *(__nv_bfloat162*)(g_H2h + r1) = __halves2bfloat162(h2, h3);
        *(__nv_bfloat162*)(g_H2l + r1) = __halves2bfloat162(l2, l3);
    }
}

// ---------------- K6: out = tanh(H2 @ W_out^T + b_out); 3 CTAs/SM -----------
// Block tile 64x128, 8 warps of 32x32. A resident (18 KB); B single-buffered
// (36 KB) -> smem 54 KB, <=85 regs => 3 CTAs/SM (24 warps) for latency hiding.
#define K6_AL 9216           /* A lo offset; A pitch 144 B, 64 rows */
#define K6_B  18432          /* B hi at 18432, B lo at 36864 */
__global__ void __launch_bounds__(256, 3) k6_mma(const float* __restrict__ b_out,
                                                 float* __restrict__ out) {
    extern __shared__ char smem[];
    uint32_t sb = smem_u32(smem);
    int t = threadIdx.x, w = t >> 5, lane = t & 31;
    int rowBase = blockIdx.x * 64;
    int colSec  = blockIdx.y * 1024;
    int wm = (w & 1) * 32, wn = (w >> 1) * 32;

    // A: 2 splits x 64 rows x 8 chunks
    for (int idx = t; idx < 1024; idx += 256) {
        int arr = idx >> 9, rem = idx & 511;
        int r = rem >> 3, cb = rem & 7;
        const __nv_bfloat16* src = (arr ? g_H2l : g_H2h)
                                 + (size_t)(rowBase + r)*64 + cb*8;
        cp16(sb + arr*K6_AL + r*144 + cb*16, src);
    }

    int g4 = lane >> 3;
    int rsel = (g4 & 1) * 8 + (lane & 7);
    int kselA = (g4 >> 1) * 8;
    int nsel = lane & 7;
    int kselB = ((lane >> 3) & 1) * 8;

    uint32_t aBase[2][2];
    #pragma unroll
    for (int mt = 0; mt < 2; mt++) {
        uint32_t off = (uint32_t)((wm + mt*16 + rsel)*144 + kselA*2);
        aBase[mt][0] = sb + off;
        aBase[mt][1] = sb + K6_AL + off;
    }
    uint32_t bOff[4];
    #pragma unroll
    for (int nt = 0; nt < 4; nt++)
        bOff[nt] = (uint32_t)((wn + nt*8 + nsel)*144 + kselB*2);

    for (int it = 0; it < 8; it++) {
        // load B tile (single buffer; cross-CTA overlap hides it)
        int nc = colSec + it*128;
        for (int idx = t; idx < 2048; idx += 256) {
            int arr = idx >> 10, rem = idx & 1023;
            int r = rem >> 3, cb = rem & 7;
            const __nv_bfloat16* src = (arr ? g_Wl : g_Wh)
                                     + (size_t)(nc + r)*64 + cb*8;
            cp16(sb + K6_B + arr*K6_B + r*144 + cb*16, src);
        }
        cp_commit();
        cp_wait0();
        __syncthreads();

        float acc[2][4][4];
        #pragma unroll
        for (int mt = 0; mt < 2; mt++)
            #pragma unroll
            for (int nt = 0; nt < 4; nt++)
                #pragma unroll
                for (int q = 0; q < 4; q++) acc[mt][nt][q] = 0.f;

        #pragma unroll
        for (int ks = 0; ks < 4; ks++) {
            uint32_t ah[2][4], al[2][4], bh[4][2], bl[4][2];
            #pragma unroll
            for (int mt = 0; mt < 2; mt++) {
                ldm4(ah[mt], aBase[mt][0] + ks*32);
                ldm4(al[mt], aBase[mt][1] + ks*32);
            }
            #pragma unroll
            for (int nt = 0; nt < 4; nt++) {
                ldm2(bh[nt], sb + K6_B + bOff[nt] + ks*32);
                ldm2(bl[nt], sb + 2*K6_B + bOff[nt] + ks*32);
            }
            #pragma unroll
            for (int mt = 0; mt < 2; mt++)
                #pragma unroll
                for (int nt = 0; nt < 4; nt++) {
                    mma_bf16(acc[mt][nt], ah[mt], bh[nt]);
                    mma_bf16(acc[mt][nt], ah[mt], bl[nt]);
                    mma_bf16(acc[mt][nt], al[mt], bh[nt]);
                }
        }

        int colT = nc + wn;
        #pragma unroll
        for (int nt = 0; nt < 4; nt++) {
            int col = colT + nt*8 + (lane & 3)*2;
            float2 bv = *(const float2*)(b_out + col);
            #pragma unroll
            for (int mt = 0; mt < 2; mt++) {
                int row0 = rowBase + wm + mt*16 + (lane >> 2);
                float2 o0, o1;
                o0.x = my_tanh(acc[mt][nt][0] + bv.x);
                o0.y = my_tanh(acc[mt][nt][1] + bv.y);
                o1.x = my_tanh(acc[mt][nt][2] + bv.x);
                o1.y = my_tanh(acc[mt][nt][3] + bv.y);
                *(float2*)(out + (size_t)row0*HC2 + col)     = o0;
                *(float2*)(out + (size_t)(row0+8)*HC2 + col) = o1;
            }
        }
        __syncthreads();   // protect single-buffered B before next load
    }
}

// ---------------- launch -----------------------------------------------------
extern "C" void kernel_launch(void* const* d_in, const int* in_sizes, int n_in,
                              void* d_out, int out_size) {
    const float* z      = (const float*)d_in[0];
    const float* W_in   = (const float*)d_in[1];
    const float* b_in   = (const float*)d_in[2];
    const float* W_out  = (const float*)d_in[3];
    const float* b_out  = (const float*)d_in[4];
    const float* emb    = (const float*)d_in[5];
    const float* wpool  = (const float*)d_in[6];
    const float* bpool  = (const float*)d_in[7];
    float* out = (float*)d_out;

    const int SM4 = 71680;        // A 2x15360 + B 2x20480
    const int SM5 = 106496;       // A 2x25600 + B 2x27648
    const int SM6 = 3 * K6_B;     // 55296
    cudaFuncSetAttribute(k4_mma,
        cudaFuncAttributeMaxDynamicSharedMemorySize, SM4);
    cudaFuncSetAttribute(k5_mma,
        cudaFuncAttributeMaxDynamicSharedMemorySize, SM5);
    cudaFuncSetAttribute(k6_mma,
        cudaFuncAttributeMaxDynamicSharedMemorySize, SM6);

    L1_prologue<<<729, 320>>>(z, W_in, b_in, W_out, emb, wpool, bpool);
    L2_cheb_ht <<<364, 320>>>();
    k4_mma     <<<dim3(4, 32, 2), 256, SM4>>>();
    k5_mma     <<<NN, 256, SM5>>>();
    k6_mma     <<<dim3(300, 4), 256, SM6>>>(b_out, out);
}

// round 16
// speedup vs baseline: 1.0104x; 1.0104x over previous
#include <cuda_runtime.h>
#include <cuda_bf16.h>
#include <math.h>
#include <cstdint>

#define NB 64
#define NN 300
#define NH 64
#define ROWS (NB*NN)        /* 19200 */
#define HC2  4096           /* HC*HC */
#define SP   320            /* padded contraction dim for S / H^T */

typedef unsigned long long ull;

// ---------------- scratch (device globals; .bss => zero-initialized) --------
__device__ float g_Hm  [NN*HC2];        // H node-major fp32 [n][b*64+c] (feeds HT)
__device__ float g_A   [NN*NN];         // supports fp32     [n][m]
__device__ float g_bn  [NN*NH];         // per-node bias     [n][o]
__device__ __align__(16) __nv_bfloat16 g_XGh[NN*12288]; // XG hi [n][b*192+j]
__device__ __align__(16) __nv_bfloat16 g_XGl[NN*12288]; // XG lo
__device__ __align__(16) __nv_bfloat16 g_Wnh[NN*12288]; // Wn hi [n][j*64+o]
__device__ __align__(16) __nv_bfloat16 g_Wnl[NN*12288]; // Wn lo
__device__ __align__(16) __nv_bfloat16 g_H2h[ROWS*NH];  // H2 hi [row][i]
__device__ __align__(16) __nv_bfloat16 g_H2l[ROWS*NH];  // H2 lo
__device__ __align__(16) __nv_bfloat16 g_Wh [HC2*NH];   // W_out hi (native [c][i])
__device__ __align__(16) __nv_bfloat16 g_Wl [HC2*NH];   // W_out lo
__device__ __align__(16) __nv_bfloat16 g_Sh [2*384*SP]; // S_k hi [k][n][m]
__device__ __align__(16) __nv_bfloat16 g_Sl [2*384*SP]; // S_k lo
__device__ __align__(16) __nv_bfloat16 g_HTh[HC2*SP];   // H^T hi [col][m]
__device__ __align__(16) __nv_bfloat16 g_HTl[HC2*SP];   // H^T lo

// tanh = 1 - 2/(e^{2x}+1): 3 FMA-pipe ops + 2 MUFU, no clamp needed.
__device__ __forceinline__ float my_tanh(float x) {
    float e = __expf(2.f * x);
    float q = __fdividef(2.f, e + 1.f);
    return 1.f - q;
}

// ---------------- stable-PTX tensor helpers ---------------------------------
__device__ __forceinline__ uint32_t smem_u32(const void* p) {
    uint32_t a;
    asm("{ .reg .u64 t; cvta.to.shared.u64 t, %1; cvt.u32.u64 %0, t; }"
        : "=r"(a) : "l"(p));
    return a;
}
__device__ __forceinline__ void ldm4(uint32_t* r, uint32_t addr) {
    asm volatile("ldmatrix.sync.aligned.m8n8.x4.shared.b16 {%0,%1,%2,%3}, [%4];"
                 : "=r"(r[0]), "=r"(r[1]), "=r"(r[2]), "=r"(r[3]) : "r"(addr));
}
__device__ __forceinline__ void ldm2(uint32_t* r, uint32_t addr) {
    asm volatile("ldmatrix.sync.aligned.m8n8.x2.shared.b16 {%0,%1}, [%2];"
                 : "=r"(r[0]), "=r"(r[1]) : "r"(addr));
}
__device__ __forceinline__ void ldm2t(uint32_t* r, uint32_t addr) {
    asm volatile("ldmatrix.sync.aligned.m8n8.x2.trans.shared.b16 {%0,%1}, [%2];"
                 : "=r"(r[0]), "=r"(r[1]) : "r"(addr));
}
__device__ __forceinline__ void mma_bf16(float* c, const uint32_t* a,
                                         const uint32_t* b) {
    asm volatile(
        "mma.sync.aligned.m16n8k16.row.col.f32.bf16.bf16.f32 "
        "{%0,%1,%2,%3}, {%4,%5,%6,%7}, {%8,%9}, {%0,%1,%2,%3};"
        : "+f"(c[0]), "+f"(c[1]), "+f"(c[2]), "+f"(c[3])
        : "r"(a[0]), "r"(a[1]), "r"(a[2]), "r"(a[3]), "r"(b[0]), "r"(b[1]));
}
__device__ __forceinline__ void cp16(uint32_t smem, const void* g) {
    asm volatile("cp.async.cg.shared.global [%0], [%1], 16;"
                 :: "r"(smem), "l"(__cvta_generic_to_global(g)));
}
__device__ __forceinline__ void cp_commit() {
    asm volatile("cp.async.commit_group;" ::: "memory");
}
__device__ __forceinline__ void cp_wait0() {
    asm volatile("cp.async.wait_group 0;" ::: "memory");
}
__device__ __forceinline__ void cp_wait1() {
    asm volatile("cp.async.wait_group 1;" ::: "memory");
}
__device__ __forceinline__ void bf16_split(float v, __nv_bfloat16& h,
                                           __nv_bfloat16& l) {
    h = __float2bfloat16(v);
    l = __float2bfloat16(v - __bfloat162float(h));
}

// ---------------- L1: all independent prologue work in one grid -------------
__global__ void __launch_bounds__(320) L1_prologue(
        const float* __restrict__ z,
        const float* __restrict__ W_in,
        const float* __restrict__ b_in,
        const float* __restrict__ W_out,
        const float* __restrict__ node_emb,
        const float* __restrict__ wpool,
        const float* __restrict__ bpool) {
    __shared__ float buf[8320];
    int t = threadIdx.x;
    int blk = blockIdx.x;
    if (blk < 300) {
        float* Wt = buf;            // [64][64]  Wt[i][o] = W_in[o][i]
        float* zs = buf + 4096;     // 64 rows of z
        int rowBase = blk * 64;
        for (int idx = t; idx < 4096; idx += 320) {
            int o = idx >> 6, i = idx & 63;
            Wt[i*64 + o] = W_in[idx];
        }
        for (int idx4 = t; idx4 < 1024; idx4 += 320)
            *(float4*)(zs + idx4*4) = *(const float4*)(z + (size_t)rowBase*64 + idx4*4);
        __syncthreads();

        if (t < 256) {
            int o = t & 63, rg = t >> 6;
            float acc[16];
            float bo = b_in[o];
            #pragma unroll
            for (int r = 0; r < 16; r++) acc[r] = bo;
            const float* zrow = zs + rg*16*64;
            #pragma unroll 4
            for (int i = 0; i < 64; i++) {
                float w = Wt[i*64 + o];
                #pragma unroll
                for (int r = 0; r < 16; r++)
                    acc[r] = fmaf(zrow[r*64 + i], w, acc[r]);
            }
            #pragma unroll
            for (int r = 0; r < 16; r++) {
                float h = fmaxf(acc[r], 0.f);
                int row = rowBase + rg*16 + r;
                int b = row / NN, n = row - b*NN;
                g_Hm[(size_t)n*HC2 + b*64 + o] = h;
                __nv_bfloat16 hh, hl;
                bf16_split(h, hh, hl);
                size_t dst = (size_t)n*12288 + b*192 + o;   // XG plane 0
                g_XGh[dst] = hh;
                g_XGl[dst] = hl;
            }
        }
    } else if (blk < 332) {
        size_t base = (size_t)(blk - 300) * 8192;
        for (int idx = t; idx < 8192; idx += 320) {
            float wv = W_out[base + idx];
            __nv_bfloat16 h, l;
            bf16_split(wv, h, l);
            g_Wh[base + idx] = h;
            g_Wl[base + idx] = l;
        }
    } else if (blk < 632) {
        int n = blk - 332;
        float* E   = buf;
        float* red = buf + 3000;
        for (int idx = t; idx < NN*10; idx += 320) E[idx] = node_emb[idx];
        if (t < 192) red[320 + t] = -1e30f;
        __syncthreads();

        float v = 0.f;
        if (t < NN) {
            float dot = 0.f;
            #pragma unroll
            for (int d = 0; d < 10; d++) dot = fmaf(E[n*10+d], E[t*10+d], dot);
            v = fmaxf(dot, 0.f);
        }
        red[t] = (t < NN) ? v : -1e30f;
        __syncthreads();
        #pragma unroll
        for (int s = 256; s > 0; s >>= 1) {
            if (t < s) red[t] = fmaxf(red[t], red[t+s]);
            __syncthreads();
        }
        float mx = red[0];
        __syncthreads();

        float ev = (t < NN) ? __expf(v - mx) : 0.f;
        red[t] = ev;
        if (t < 192) red[320 + t] = 0.f;
        __syncthreads();
        #pragma unroll
        for (int s = 256; s > 0; s >>= 1) {
            if (t < s) red[t] += red[t+s];
            __syncthreads();
        }
        float inv = 1.f / red[0];
        if (t < NN) {
            float a = ev * inv;
            g_A[n*NN + t] = a;
            __nv_bfloat16 h, l;
            bf16_split(a, h, l);
            g_Sh[n*SP + t] = h;
            g_Sl[n*SP + t] = l;
        }
    } else if (blk < 728) {
        int jt = (blk - 632) * 128;
        float* E   = buf;
        float* wps = buf + 3000;
        for (int idx = t; idx < NN*10; idx += 320) E[idx] = node_emb[idx];
        for (int idx = t; idx < 1280; idx += 320) {
            int d = idx >> 7, jj = idx & 127;
            wps[idx] = wpool[(size_t)d*12288 + jt + jj];
        }
        __syncthreads();
        if (t < 256) {
            int jj = t & 127, half = t >> 7;
            const float* w0 = wps + jj;
            for (int n = half; n < NN; n += 2) {
                float acc = 0.f;
                const float* en = E + n*10;
                #pragma unroll
                for (int d = 0; d < 10; d++)
                    acc = fmaf(en[d], w0[d*128], acc);
                __nv_bfloat16 h, l;
                bf16_split(acc, h, l);
                size_t dst = (size_t)n*12288 + jt + jj;
                g_Wnh[dst] = h;
                g_Wnl[dst] = l;
            }
        }
    } else {
        float* E   = buf;
        float* wps = buf + 3000;
        for (int idx = t; idx < 640; idx += 320) wps[idx] = bpool[idx];
        for (int idx = t; idx < NN*10; idx += 320) E[idx] = node_emb[idx];
        __syncthreads();
        for (int idx = t; idx < NN*64; idx += 320) {
            int n = idx >> 6, o = idx & 63;
            float acc = 0.f;
            #pragma unroll
            for (int d = 0; d < 10; d++)
                acc = fmaf(E[n*10+d], wps[d*64 + o], acc);
            g_bn[idx] = acc;
        }
    }
}

// ---------------- L2: Chebyshev (0..299) + H transpose/split (300..363) -----
__global__ void __launch_bounds__(320) L2_cheb_ht() {
    __shared__ float buf[4160];
    int t = threadIdx.x;
    int blk = blockIdx.x;
    if (blk < 300) {
        int n = blk;
        float* arow = buf;
        for (int idx = t; idx < NN; idx += 320) arow[idx] = g_A[n*NN + idx];
        __syncthreads();
        if (t < NN) {
            float acc = 0.f;
            #pragma unroll 4
            for (int p = 0; p < NN; p++)
                acc = fmaf(arow[p], g_A[p*NN + t], acc);
            float v = 2.f*acc - ((t == n) ? 1.f : 0.f);
            __nv_bfloat16 h, l;
            bf16_split(v, h, l);
            g_Sh[384*SP + n*SP + t] = h;
            g_Sl[384*SP + n*SP + t] = l;
        }
    } else {
        float* Ts = buf;            // [64][65]
        int cb = (blk - 300) * 64;
        for (int m0 = 0; m0 < NN; m0 += 64) {
            int mc = min(64, NN - m0);
            __syncthreads();
            for (int idx = t; idx < 4096; idx += 320) {
                int mm = idx >> 6, c = idx & 63;
                if (mm < mc)
                    Ts[mm*65 + c] = g_Hm[(size_t)(m0+mm)*HC2 + cb + c];
            }
            __syncthreads();
            for (int idx = t; idx < 4096; idx += 320) {
                int c = idx >> 6, mm = idx & 63;
                if (mm < mc) {
                    __nv_bfloat16 h, l;
                    bf16_split(Ts[mm*65 + c], h, l);
                    g_HTh[(size_t)(cb+c)*SP + m0 + mm] = h;
                    g_HTl[(size_t)(cb+c)*SP + m0 + mm] = l;
                }
            }
        }
    }
}

// ---------------- K4: XG_k = S_k @ Hm via mma.sync; 96-row tiles ------------
__global__ void __launch_bounds__(256, 2) k4_mma() {
    extern __shared__ char smem[];
    uint32_t sb = smem_u32(smem);
    int t = threadIdx.x, w = t >> 5, lane = t & 31;
    int rowBase = blockIdx.x * 96;
    int colBase = blockIdx.y * 128;
    int kz = blockIdx.z;
    const __nv_bfloat16* Sh = g_Sh + (size_t)kz*384*SP;
    const __nv_bfloat16* Sl = g_Sl + (size_t)kz*384*SP;
    int wm = (w & 1) * 48, wn = (w >> 1) * 32;

    int g4 = lane >> 3;
    int rsel = (g4 & 1) * 8 + (lane & 7);
    int kselA = (g4 >> 1) * 8;
    int nsel = lane & 7;
    int kselB = ((lane >> 3) & 1) * 8;
    uint32_t aOff[3], bOff[4];
    #pragma unroll
    for (int mt = 0; mt < 3; mt++)
        aOff[mt] = (uint32_t)((wm + mt*16 + rsel)*80 + kselA*2);
    #pragma unroll
    for (int nt = 0; nt < 4; nt++)
        bOff[nt] = (uint32_t)((wn + nt*8 + nsel)*80 + kselB*2);

    float acc[3][4][4];
    #pragma unroll
    for (int mt = 0; mt < 3; mt++)
        #pragma unroll
        for (int nt = 0; nt < 4; nt++)
            #pragma unroll
            for (int q = 0; q < 4; q++) acc[mt][nt][q] = 0.f;

    const int NC = 10;
    for (int idx = t; idx < 768; idx += 256) {
        int arr = idx / 384, rem = idx % 384;
        int r = rem >> 2, c4 = rem & 3;
        cp16(sb + arr*7680 + r*80 + c4*16,
             (arr ? Sl : Sh) + (size_t)(rowBase + r)*SP + c4*8);
    }
    for (int idx = t; idx < 1024; idx += 256) {
        int arr = idx >> 9, rem = idx & 511;
        int r = rem >> 2, c4 = rem & 3;
        cp16(sb + 30720 + arr*10240 + r*80 + c4*16,
             (arr ? g_HTl : g_HTh) + (size_t)(colBase + r)*SP + c4*8);
    }
    cp_commit();

    for (int c = 0; c < NC; c++) {
        int stage = c & 1;
        if (c + 1 < NC) {
            int m0 = (c + 1) * 32, ns = (c + 1) & 1;
            for (int idx = t; idx < 768; idx += 256) {
                int arr = idx / 384, rem = idx % 384;
                int r = rem >> 2, c4 = rem & 3;
                cp16(sb + ns*15360 + arr*7680 + r*80 + c4*16,
                     (arr ? Sl : Sh) + (size_t)(rowBase + r)*SP + m0 + c4*8);
            }
            for (int idx = t; idx < 1024; idx += 256) {
                int arr = idx >> 9, rem = idx & 511;
                int r = rem >> 2, c4 = rem & 3;
                cp16(sb + 30720 + ns*20480 + arr*10240 + r*80 + c4*16,
                     (arr ? g_HTl : g_HTh) + (size_t)(colBase + r)*SP + m0 + c4*8);
            }
            cp_commit();
            cp_wait1();
        } else {
            cp_wait0();
        }
        __syncthreads();

        uint32_t sA = sb + stage*15360;
        uint32_t sB = sb + 30720 + stage*20480;
        #pragma unroll
        for (int ks = 0; ks < 2; ks++) {
            uint32_t ah[3][4], al[3][4], bh[4][2], bl[4][2];
            #pragma unroll
            for (int mt = 0; mt < 3; mt++) {
                ldm4(ah[mt], sA + aOff[mt] + ks*32);
                ldm4(al[mt], sA + 7680 + aOff[mt] + ks*32);
            }
            #pragma unroll
            for (int nt = 0; nt < 4; nt++) {
                ldm2(bh[nt], sB + bOff[nt] + ks*32);
                ldm2(bl[nt], sB + 10240 + bOff[nt] + ks*32);
            }
            #pragma unroll
            for (int mt = 0; mt < 3; mt++)
                #pragma unroll
                for (int nt = 0; nt < 4; nt++) {
                    mma_bf16(acc[mt][nt], ah[mt], bh[nt]);
                    mma_bf16(acc[mt][nt], ah[mt], bl[nt]);
                    mma_bf16(acc[mt][nt], al[mt], bh[nt]);
                }
        }
        __syncthreads();
    }

    int plane = (kz + 1) * 64;
    #pragma unroll
    for (int nt = 0; nt < 4; nt++) {
        int col = colBase + wn + nt*8 + (lane & 3)*2;
        int b = col >> 6, cc = col & 63;
        size_t boff = (size_t)b*192 + plane + cc;
        #pragma unroll
        for (int mt = 0; mt < 3; mt++) {
            int n0 = rowBase + wm + mt*16 + (lane >> 2);
            if (n0 < NN) {
                __nv_bfloat16 h0, l0, h1, l1;
                bf16_split(acc[mt][nt][0], h0, l0);
                bf16_split(acc[mt][nt][1], h1, l1);
                *(__nv_bfloat162*)(g_XGh + (size_t)n0*12288 + boff) = __halves2bfloat162(h0, h1);
                *(__nv_bfloat162*)(g_XGl + (size_t)n0*12288 + boff) = __halves2bfloat162(l0, l1);
            }
            if (n0 + 8 < NN) {
                __nv_bfloat16 h0, l0, h1, l1;
                bf16_split(acc[mt][nt][2], h0, l0);
                bf16_split(acc[mt][nt][3], h1, l1);
                *(__nv_bfloat162*)(g_XGh + (size_t)(n0+8)*12288 + boff) = __halves2bfloat162(h0, h1);
                *(__nv_bfloat162*)(g_XGl + (size_t)(n0+8)*12288 + boff) = __halves2bfloat162(l0, l1);
            }
        }
    }
}

// ---------------- K5: per-node [64,192]@[192,64] via mma.sync (R13 shape) ---
#define K5_AL 25600
#define K5_BH 51200
#define K5_BL 78848
__global__ void __launch_bounds__(256, 2) k5_mma() {
    extern __shared__ char smem[];
    uint32_t sb = smem_u32(smem);
    int t = threadIdx.x, w = t >> 5, lane = t & 31;
    int n = blockIdx.x;

    const __nv_bfloat16* Ah = g_XGh + (size_t)n*12288;
    const __nv_bfloat16* Al = g_XGl + (size_t)n*12288;
    const __nv_bfloat16* Bh = g_Wnh + (size_t)n*12288;
    const __nv_bfloat16* Bl = g_Wnl + (size_t)n*12288;

    for (int idx = t; idx < 1536; idx += 256) {       // A: 64 rows x 24 chunks
        int r = idx / 24, cc = idx - r*24;
        cp16(sb + r*400 + cc*16,          Ah + r*192 + cc*8);
        cp16(sb + K5_AL + r*400 + cc*16,  Al + r*192 + cc*8);
    }
    for (int idx = t; idx < 1536; idx += 256) {       // B: 192 rows x 8 chunks
        int r = idx >> 3, cc = idx & 7;
        cp16(sb + K5_BH + r*144 + cc*16,  Bh + r*64 + cc*8);
        cp16(sb + K5_BL + r*144 + cc*16,  Bl + r*64 + cc*8);
    }
    cp_commit();
    cp_wait0();
    __syncthreads();

    int wm = (w & 3) * 16, wn = (w >> 2) * 32;
    int g4 = lane >> 3;
    int rsel = (g4 & 1) * 8 + (lane & 7);
    int kselA = (g4 >> 1) * 8;
    uint32_t aAddrH = sb + (uint32_t)((wm + rsel)*400 + kselA*2);
    uint32_t aAddrL = aAddrH + K5_AL;
    uint32_t bRow = (uint32_t)(lane & 15);
    uint32_t bAddr[4];
    #pragma unroll
    for (int nt = 0; nt < 4; nt++)
        bAddr[nt] = sb + K5_BH + bRow*144 + (uint32_t)((wn + nt*8)*2);

    float acc[4][4];
    #pragma unroll
    for (int nt = 0; nt < 4; nt++)
        #pragma unroll
        for (int q = 0; q < 4; q++) acc[nt][q] = 0.f;

    #pragma unroll
    for (int kc = 0; kc < 12; kc++) {
        uint32_t ah[4], al[4];
        ldm4(ah, aAddrH + kc*32);
        ldm4(al, aAddrL + kc*32);
        #pragma unroll
        for (int nt = 0; nt < 4; nt++) {
            uint32_t bh[2], bl[2];
            ldm2t(bh, bAddr[nt] + (uint32_t)(kc*16*144));
            ldm2t(bl, bAddr[nt] + (uint32_t)(K5_BL - K5_BH) + (uint32_t)(kc*16*144));
            mma_bf16(acc[nt], ah, bh);
            mma_bf16(acc[nt], ah, bl);
            mma_bf16(acc[nt], al, bh);
        }
    }

    #pragma unroll
    for (int nt = 0; nt < 4; nt++) {
        int o = wn + nt*8 + (lane & 3)*2;
        float2 bv = *(const float2*)(g_bn + n*64 + o);
        int b0 = wm + (lane >> 2);
        float v0 = acc[nt][0] + bv.x, v1 = acc[nt][1] + bv.y;
        float v2 = acc[nt][2] + bv.x, v3 = acc[nt][3] + bv.y;
        __nv_bfloat16 h0, l0, h1, l1, h2, l2, h3, l3;
        bf16_split(v0, h0, l0); bf16_split(v1, h1, l1);
        bf16_split(v2, h2, l2); bf16_split(v3, h3, l3);
        size_t r0 = ((size_t)(b0*NN + n))*64 + o;
        size_t r1 = ((size_t)((b0+8)*NN + n))*64 + o;
        *(__nv_bfloat162*)(g_H2h + r0) = __halves2bfloat162(h0, h1);
        *(__nv_bfloat162*)(g_H2l + r0) = __halves2bfloat162(l0, l1);
        *(__nv_bfloat162*)(g_H2h + r1) = __halves2bfloat162(h2, h3);
        *(__nv_bfloat162*)(g_H2l + r1) = __halves2bfloat162(l2, l3);
    }
}

// ---------------- K6: out = tanh(H2 @ W_out^T + b_out) via mma.sync bf16 ----
// R14 config: 128x128 tile, double-buffered B, 2 CTAs/SM, grid (150,4).
#define ASPLIT 18432                   /* 128*72*2 bytes per split */
__global__ void __launch_bounds__(256, 2) k6_mma(const float* __restrict__ b_out,
                                                 float* __restrict__ out) {
    extern __shared__ char smem[];
    uint32_t sb = smem_u32(smem);
    const int OFF_B = 2 * ASPLIT;
    int t = threadIdx.x, w = t >> 5, lane = t & 31;
    int rowBase = blockIdx.x * 128;
    int colSec  = blockIdx.y * 1024;
    int wm = (w & 1) * 64, wn = (w >> 1) * 32;

    for (int idx = t; idx < 2048; idx += 256) {
        int arr = idx >> 10, rem = idx & 1023;
        int r = rem >> 3, cb = rem & 7;
        const __nv_bfloat16* src = (arr ? g_H2l : g_H2h)
                                 + (size_t)(rowBase + r)*64 + cb*8;
        cp16(sb + arr*ASPLIT + r*144 + cb*16, src);
    }
    for (int idx = t; idx < 2048; idx += 256) {
        int arr = idx >> 10, rem = idx & 1023;
        int r = rem >> 3, cb = rem & 7;
        const __nv_bfloat16* src = (arr ? g_Wl : g_Wh)
                                 + (size_t)(colSec + r)*64 + cb*8;
        cp16(sb + OFF_B + arr*ASPLIT + r*144 + cb*16, src);
    }
    cp_commit();
    cp_wait0();
    __syncthreads();

    int g4 = lane >> 3;
    int rsel = (g4 & 1) * 8 + (lane & 7);
    int kselA = (g4 >> 1) * 8;
    int g2 = (lane >> 3) & 1;
    int nsel = lane & 7;
    int kselB = g2 * 8;

    uint32_t aBase[4][2];
    #pragma unroll
    for (int mt = 0; mt < 4; mt++) {
        uint32_t off = (uint32_t)((wm + mt*16 + rsel)*144 + kselA*2);
        aBase[mt][0] = sb + off;
        aBase[mt][1] = sb + ASPLIT + off;
    }
    uint32_t bOff[4];
    #pragma unroll
    for (int nt = 0; nt < 4; nt++)
        bOff[nt] = (uint32_t)((wn + nt*8 + nsel)*144 + kselB*2);

    for (int it = 0; it < 8; it++) {
        int stage = it & 1;
        if (it + 1 < 8) {
            int nc = colSec + (it + 1) * 128;
            for (int idx = t; idx < 2048; idx += 256) {
                int arr = idx >> 10, rem = idx & 1023;
                int r = rem >> 3, cb = rem & 7;
                const __nv_bfloat16* src = (arr ? g_Wl : g_Wh)
                                         + (size_t)(nc + r)*64 + cb*8;
                cp16(sb + OFF_B + (stage^1)*2*ASPLIT + arr*ASPLIT + r*144 + cb*16, src);
            }
        }
        cp_commit();

        float acc[4][4][4];
        #pragma unroll
        for (int mt = 0; mt < 4; mt++)
            #pragma unroll
            for (int nt = 0; nt < 4; nt++)
                #pragma unroll
                for (int q = 0; q < 4; q++) acc[mt][nt][q] = 0.f;

        uint32_t bStage = sb + OFF_B + stage*2*ASPLIT;
        #pragma unroll
        for (int ks = 0; ks < 4; ks++) {
            uint32_t ah[4][4], al[4][4], bh[4][2], bl[4][2];
            #pragma unroll
            for (int mt = 0; mt < 4; mt++) {
                ldm4(ah[mt], aBase[mt][0] + ks*32);
                ldm4(al[mt], aBase[mt][1] + ks*32);
            }
            #pragma unroll
            for (int nt = 0; nt < 4; nt++) {
                ldm2(bh[nt], bStage + bOff[nt] + ks*32);
                ldm2(bl[nt], bStage + ASPLIT + bOff[nt] + ks*32);
            }
            #pragma unroll
            for (int mt = 0; mt < 4; mt++)
                #pragma unroll
                for (int nt = 0; nt < 4; nt++) {
                    mma_bf16(acc[mt][nt], ah[mt], bh[nt]);
                    mma_bf16(acc[mt][nt], ah[mt], bl[nt]);
                    mma_bf16(acc[mt][nt], al[mt], bh[nt]);
                }
        }

        int colT = colSec + it*128 + wn;
        #pragma unroll
        for (int nt = 0; nt < 4; nt++) {
            int col = colT + nt*8 + (lane & 3)*2;
            float2 bv = *(const float2*)(b_out + col);
            #pragma unroll
            for (int mt = 0; mt < 4; mt++) {
                int row0 = rowBase + wm + mt*16 + (lane >> 2);
                float2 o0, o1;
                o0.x = my_tanh(acc[mt][nt][0] + bv.x);
                o0.y = my_tanh(acc[mt][nt][1] + bv.y);
                o1.x = my_tanh(acc[mt][nt][2] + bv.x);
                o1.y = my_tanh(acc[mt][nt][3] + bv.y);
                *(float2*)(out + (size_t)row0*HC2 + col)       = o0;
                *(float2*)(out + (size_t)(row0+8)*HC2 + col)   = o1;
            }
        }

        cp_wait0();
        __syncthreads();
    }
}

// ---------------- launch -----------------------------------------------------
extern "C" void kernel_launch(void* const* d_in, const int* in_sizes, int n_in,
                              void* d_out, int out_size) {
    const float* z      = (const float*)d_in[0];
    const float* W_in   = (const float*)d_in[1];
    const float* b_in   = (const float*)d_in[2];
    const float* W_out  = (const float*)d_in[3];
    const float* b_out  = (const float*)d_in[4];
    const float* emb    = (const float*)d_in[5];
    const float* wpool  = (const float*)d_in[6];
    const float* bpool  = (const float*)d_in[7];
    float* out = (float*)d_out;

    const int SM4 = 71680;        // A 2x15360 + B 2x20480
    const int SM5 = 106496;       // A 2x25600 + B 2x27648
    const int SM6 = 6 * ASPLIT;   // 110592
    cudaFuncSetAttribute(k4_mma,
        cudaFuncAttributeMaxDynamicSharedMemorySize, SM4);
    cudaFuncSetAttribute(k5_mma,
        cudaFuncAttributeMaxDynamicSharedMemorySize, SM5);
    cudaFuncSetAttribute(k6_mma,
        cudaFuncAttributeMaxDynamicSharedMemorySize, SM6);

    L1_prologue<<<729, 320>>>(z, W_in, b_in, W_out, emb, wpool, bpool);
    L2_cheb_ht <<<364, 320>>>();
    k4_mma     <<<dim3(4, 32, 2), 256, SM4>>>();
    k5_mma     <<<NN, 256, SM5>>>();
    k6_mma     <<<dim3(150, 4), 256, SM6>>>(b_out, out);
}

// round 17
// speedup vs baseline: 1.1223x; 1.1108x over previous
#include <cuda_runtime.h>
#include <cuda_bf16.h>
#include <cuda_fp16.h>
#include <math.h>
#include <cstdint>

#define NB 64
#define NN 300
#define NH 64
#define ROWS (NB*NN)        /* 19200 */
#define HC2  4096           /* HC*HC */
#define SP   320            /* padded contraction dim for S / H^T */

typedef unsigned long long ull;

// ---------------- scratch (device globals; .bss => zero-initialized) --------
__device__ float g_Hm  [NN*HC2];        // H node-major fp32 [n][b*64+c] (feeds HT)
__device__ float g_A   [NN*NN];         // supports fp32     [n][m]
__device__ float g_bn  [NN*NH];         // per-node bias     [n][o]
__device__ __align__(16) __nv_bfloat16 g_XGh[NN*12288]; // XG hi [n][b*192+j]
__device__ __align__(16) __nv_bfloat16 g_XGl[NN*12288]; // XG lo
__device__ __align__(16) __nv_bfloat16 g_Wnh[NN*12288]; // Wn hi [n][j*64+o]
__device__ __align__(16) __nv_bfloat16 g_Wnl[NN*12288]; // Wn lo
__device__ __align__(16) __half g_H2f[ROWS*NH];         // H2 fp16 (single) [row][i]
__device__ __align__(16) __half g_Wfh[HC2*NH];          // W_out fp16 hi ([c][i])
__device__ __align__(16) __half g_Wfl[HC2*NH];          // W_out fp16 lo
__device__ __align__(16) __nv_bfloat16 g_Sh [2*384*SP]; // S_k hi [k][n][m]
__device__ __align__(16) __nv_bfloat16 g_Sl [2*384*SP]; // S_k lo
__device__ __align__(16) __nv_bfloat16 g_HTh[HC2*SP];   // H^T hi [col][m]
__device__ __align__(16) __nv_bfloat16 g_HTl[HC2*SP];   // H^T lo

// tanh = 1 - 2/(e^{2x}+1): 3 FMA-pipe ops + 2 MUFU, no clamp needed.
__device__ __forceinline__ float my_tanh(float x) {
    float e = __expf(2.f * x);
    float q = __fdividef(2.f, e + 1.f);
    return 1.f - q;
}

// ---------------- stable-PTX tensor helpers ---------------------------------
__device__ __forceinline__ uint32_t smem_u32(const void* p) {
    uint32_t a;
    asm("{ .reg .u64 t; cvta.to.shared.u64 t, %1; cvt.u32.u64 %0, t; }"
        : "=r"(a) : "l"(p));
    return a;
}
__device__ __forceinline__ void ldm4(uint32_t* r, uint32_t addr) {
    asm volatile("ldmatrix.sync.aligned.m8n8.x4.shared.b16 {%0,%1,%2,%3}, [%4];"
                 : "=r"(r[0]), "=r"(r[1]), "=r"(r[2]), "=r"(r[3]) : "r"(addr));
}
__device__ __forceinline__ void ldm2(uint32_t* r, uint32_t addr) {
    asm volatile("ldmatrix.sync.aligned.m8n8.x2.shared.b16 {%0,%1}, [%2];"
                 : "=r"(r[0]), "=r"(r[1]) : "r"(addr));
}
__device__ __forceinline__ void ldm2t(uint32_t* r, uint32_t addr) {
    asm volatile("ldmatrix.sync.aligned.m8n8.x2.trans.shared.b16 {%0,%1}, [%2];"
                 : "=r"(r[0]), "=r"(r[1]) : "r"(addr));
}
__device__ __forceinline__ void mma_bf16(float* c, const uint32_t* a,
                                         const uint32_t* b) {
    asm volatile(
        "mma.sync.aligned.m16n8k16.row.col.f32.bf16.bf16.f32 "
        "{%0,%1,%2,%3}, {%4,%5,%6,%7}, {%8,%9}, {%0,%1,%2,%3};"
        : "+f"(c[0]), "+f"(c[1]), "+f"(c[2]), "+f"(c[3])
        : "r"(a[0]), "r"(a[1]), "r"(a[2]), "r"(a[3]), "r"(b[0]), "r"(b[1]));
}
__device__ __forceinline__ void mma_f16(float* c, const uint32_t* a,
                                        const uint32_t* b) {
    asm volatile(
        "mma.sync.aligned.m16n8k16.row.col.f32.f16.f16.f32 "
        "{%0,%1,%2,%3}, {%4,%5,%6,%7}, {%8,%9}, {%0,%1,%2,%3};"
        : "+f"(c[0]), "+f"(c[1]), "+f"(c[2]), "+f"(c[3])
        : "r"(a[0]), "r"(a[1]), "r"(a[2]), "r"(a[3]), "r"(b[0]), "r"(b[1]));
}
__device__ __forceinline__ void cp16(uint32_t smem, const void* g) {
    asm volatile("cp.async.cg.shared.global [%0], [%1], 16;"
                 :: "r"(smem), "l"(__cvta_generic_to_global(g)));
}
__device__ __forceinline__ void cp_commit() {
    asm volatile("cp.async.commit_group;" ::: "memory");
}
__device__ __forceinline__ void cp_wait0() {
    asm volatile("cp.async.wait_group 0;" ::: "memory");
}
__device__ __forceinline__ void cp_wait1() {
    asm volatile("cp.async.wait_group 1;" ::: "memory");
}
__device__ __forceinline__ void bf16_split(float v, __nv_bfloat16& h,
                                           __nv_bfloat16& l) {
    h = __float2bfloat16(v);
    l = __float2bfloat16(v - __bfloat162float(h));
}
__device__ __forceinline__ void fp16_split(float v, __half& h, __half& l) {
    h = __float2half(v);
    l = __float2half(v - __half2float(h));
}

// ---------------- L1: all independent prologue work in one grid -------------
__global__ void __launch_bounds__(320) L1_prologue(
        const float* __restrict__ z,
        const float* __restrict__ W_in,
        const float* __restrict__ b_in,
        const float* __restrict__ W_out,
        const float* __restrict__ node_emb,
        const float* __restrict__ wpool,
        const float* __restrict__ bpool) {
    __shared__ float buf[8320];
    int t = threadIdx.x;
    int blk = blockIdx.x;
    if (blk < 300) {
        float* Wt = buf;            // [64][64]  Wt[i][o] = W_in[o][i]
        float* zs = buf + 4096;     // 64 rows of z
        int rowBase = blk * 64;
        for (int idx = t; idx < 4096; idx += 320) {
            int o = idx >> 6, i = idx & 63;
            Wt[i*64 + o] = W_in[idx];
        }
        for (int idx4 = t; idx4 < 1024; idx4 += 320)
            *(float4*)(zs + idx4*4) = *(const float4*)(z + (size_t)rowBase*64 + idx4*4);
        __syncthreads();

        if (t < 256) {
            int o = t & 63, rg = t >> 6;
            float acc[16];
            float bo = b_in[o];
            #pragma unroll
            for (int r = 0; r < 16; r++) acc[r] = bo;
            const float* zrow = zs + rg*16*64;
            #pragma unroll 4
            for (int i = 0; i < 64; i++) {
                float w = Wt[i*64 + o];
                #pragma unroll
                for (int r = 0; r < 16; r++)
                    acc[r] = fmaf(zrow[r*64 + i], w, acc[r]);
            }
            #pragma unroll
            for (int r = 0; r < 16; r++) {
                float h = fmaxf(acc[r], 0.f);
                int row = rowBase + rg*16 + r;
                int b = row / NN, n = row - b*NN;
                g_Hm[(size_t)n*HC2 + b*64 + o] = h;
                __nv_bfloat16 hh, hl;
                bf16_split(h, hh, hl);
                size_t dst = (size_t)n*12288 + b*192 + o;   // XG plane 0
                g_XGh[dst] = hh;
                g_XGl[dst] = hl;
            }
        }
    } else if (blk < 332) {
        size_t base = (size_t)(blk - 300) * 8192;
        for (int idx = t; idx < 8192; idx += 320) {
            float wv = W_out[base + idx];
            __half h, l;
            fp16_split(wv, h, l);
            g_Wfh[base + idx] = h;
            g_Wfl[base + idx] = l;
        }
    } else if (blk < 632) {
        int n = blk - 332;
        float* E   = buf;
        float* red = buf + 3000;
        for (int idx = t; idx < NN*10; idx += 320) E[idx] = node_emb[idx];
        if (t < 192) red[320 + t] = -1e30f;
        __syncthreads();

        float v = 0.f;
        if (t < NN) {
            float dot = 0.f;
            #pragma unroll
            for (int d = 0; d < 10; d++) dot = fmaf(E[n*10+d], E[t*10+d], dot);
            v = fmaxf(dot, 0.f);
        }
        red[t] = (t < NN) ? v : -1e30f;
        __syncthreads();
        #pragma unroll
        for (int s = 256; s > 0; s >>= 1) {
            if (t < s) red[t] = fmaxf(red[t], red[t+s]);
            __syncthreads();
        }
        float mx = red[0];
        __syncthreads();

        float ev = (t < NN) ? __expf(v - mx) : 0.f;
        red[t] = ev;
        if (t < 192) red[320 + t] = 0.f;
        __syncthreads();
        #pragma unroll
        for (int s = 256; s > 0; s >>= 1) {
            if (t < s) red[t] += red[t+s];
            __syncthreads();
        }
        float inv = 1.f / red[0];
        if (t < NN) {
            float a = ev * inv;
            g_A[n*NN + t] = a;
            __nv_bfloat16 h, l;
            bf16_split(a, h, l);
            g_Sh[n*SP + t] = h;
            g_Sl[n*SP + t] = l;
        }
    } else if (blk < 728) {
        int jt = (blk - 632) * 128;
        float* E   = buf;
        float* wps = buf + 3000;
        for (int idx = t; idx < NN*10; idx += 320) E[idx] = node_emb[idx];
        for (int idx = t; idx < 1280; idx += 320) {
            int d = idx >> 7, jj = idx & 127;
            wps[idx] = wpool[(size_t)d*12288 + jt + jj];
        }
        __syncthreads();
        if (t < 256) {
            int jj = t & 127, half = t >> 7;
            const float* w0 = wps + jj;
            for (int n = half; n < NN; n += 2) {
                float acc = 0.f;
                const float* en = E + n*10;
                #pragma unroll
                for (int d = 0; d < 10; d++)
                    acc = fmaf(en[d], w0[d*128], acc);
                __nv_bfloat16 h, l;
                bf16_split(acc, h, l);
                size_t dst = (size_t)n*12288 + jt + jj;
                g_Wnh[dst] = h;
                g_Wnl[dst] = l;
            }
        }
    } else {
        float* E   = buf;
        float* wps = buf + 3000;
        for (int idx = t; idx < 640; idx += 320) wps[idx] = bpool[idx];
        for (int idx = t; idx < NN*10; idx += 320) E[idx] = node_emb[idx];
        __syncthreads();
        for (int idx = t; idx < NN*64; idx += 320) {
            int n = idx >> 6, o = idx & 63;
            float acc = 0.f;
            #pragma unroll
            for (int d = 0; d < 10; d++)
                acc = fmaf(E[n*10+d], wps[d*64 + o], acc);
            g_bn[idx] = acc;
        }
    }
}

// ---------------- L2: Chebyshev (0..299) + H transpose/split (300..363) -----
__global__ void __launch_bounds__(320) L2_cheb_ht() {
    __shared__ float buf[4160];
    int t = threadIdx.x;
    int blk = blockIdx.x;
    if (blk < 300) {
        int n = blk;
        float* arow = buf;
        for (int idx = t; idx < NN; idx += 320) arow[idx] = g_A[n*NN + idx];
        __syncthreads();
        if (t < NN) {
            float acc = 0.f;
            #pragma unroll 4
            for (int p = 0; p < NN; p++)
                acc = fmaf(arow[p], g_A[p*NN + t], acc);
            float v = 2.f*acc - ((t == n) ? 1.f : 0.f);
            __nv_bfloat16 h, l;
            bf16_split(v, h, l);
            g_Sh[384*SP + n*SP + t] = h;
            g_Sl[384*SP + n*SP + t] = l;
        }
    } else {
        float* Ts = buf;            // [64][65]
        int cb = (blk - 300) * 64;
        for (int m0 = 0; m0 < NN; m0 += 64) {
            int mc = min(64, NN - m0);
            __syncthreads();
            for (int idx = t; idx < 4096; idx += 320) {
                int mm = idx >> 6, c = idx & 63;
                if (mm < mc)
                    Ts[mm*65 + c] = g_Hm[(size_t)(m0+mm)*HC2 + cb + c];
            }
            __syncthreads();
            for (int idx = t; idx < 4096; idx += 320) {
                int c = idx >> 6, mm = idx & 63;
                if (mm < mc) {
                    __nv_bfloat16 h, l;
                    bf16_split(Ts[mm*65 + c], h, l);
                    g_HTh[(size_t)(cb+c)*SP + m0 + mm] = h;
                    g_HTl[(size_t)(cb+c)*SP + m0 + mm] = l;
                }
            }
        }
    }
}

// ---------------- K4: XG_k = S_k @ Hm via mma.sync; 96-row tiles ------------
__global__ void __launch_bounds__(256, 2) k4_mma() {
    extern __shared__ char smem[];
    uint32_t sb = smem_u32(smem);
    int t = threadIdx.x, w = t >> 5, lane = t & 31;
    int rowBase = blockIdx.x * 96;
    int colBase = blockIdx.y * 128;
    int kz = blockIdx.z;
    const __nv_bfloat16* Sh = g_Sh + (size_t)kz*384*SP;
    const __nv_bfloat16* Sl = g_Sl + (size_t)kz*384*SP;
    int wm = (w & 1) * 48, wn = (w >> 1) * 32;

    int g4 = lane >> 3;
    int rsel = (g4 & 1) * 8 + (lane & 7);
    int kselA = (g4 >> 1) * 8;
    int nsel = lane & 7;
    int kselB = ((lane >> 3) & 1) * 8;
    uint32_t aOff[3], bOff[4];
    #pragma unroll
    for (int mt = 0; mt < 3; mt++)
        aOff[mt] = (uint32_t)((wm + mt*16 + rsel)*80 + kselA*2);
    #pragma unroll
    for (int nt = 0; nt < 4; nt++)
        bOff[nt] = (uint32_t)((wn + nt*8 + nsel)*80 + kselB*2);

    float acc[3][4][4];
    #pragma unroll
    for (int mt = 0; mt < 3; mt++)
        #pragma unroll
        for (int nt = 0; nt < 4; nt++)
            #pragma unroll
            for (int q = 0; q < 4; q++) acc[mt][nt][q] = 0.f;

    const int NC = 10;
    for (int idx = t; idx < 768; idx += 256) {
        int arr = idx / 384, rem = idx % 384;
        int r = rem >> 2, c4 = rem & 3;
        cp16(sb + arr*7680 + r*80 + c4*16,
             (arr ? Sl : Sh) + (size_t)(rowBase + r)*SP + c4*8);
    }
    for (int idx = t; idx < 1024; idx += 256) {
        int arr = idx >> 9, rem = idx & 511;
        int r = rem >> 2, c4 = rem & 3;
        cp16(sb + 30720 + arr*10240 + r*80 + c4*16,
             (arr ? g_HTl : g_HTh) + (size_t)(colBase + r)*SP + c4*8);
    }
    cp_commit();

    for (int c = 0; c < NC; c++) {
        int stage = c & 1;
        if (c + 1 < NC) {
            int m0 = (c + 1) * 32, ns = (c + 1) & 1;
            for (int idx = t; idx < 768; idx += 256) {
                int arr = idx / 384, rem = idx % 384;
                int r = rem >> 2, c4 = rem & 3;
                cp16(sb + ns*15360 + arr*7680 + r*80 + c4*16,
                     (arr ? Sl : Sh) + (size_t)(rowBase + r)*SP + m0 + c4*8);
            }
            for (int idx = t; idx < 1024; idx += 256) {
                int arr = idx >> 9, rem = idx & 511;
                int r = rem >> 2, c4 = rem & 3;
                cp16(sb + 30720 + ns*20480 + arr*10240 + r*80 + c4*16,
                     (arr ? g_HTl : g_HTh) + (size_t)(colBase + r)*SP + m0 + c4*8);
            }
            cp_commit();
            cp_wait1();
        } else {
            cp_wait0();
        }
        __syncthreads();

        uint32_t sA = sb + stage*15360;
        uint32_t sB = sb + 30720 + stage*20480;
        #pragma unroll
        for (int ks = 0; ks < 2; ks++) {
            uint32_t ah[3][4], al[3][4], bh[4][2], bl[4][2];
            #pragma unroll
            for (int mt = 0; mt < 3; mt++) {
                ldm4(ah[mt], sA + aOff[mt] + ks*32);
                ldm4(al[mt], sA + 7680 + aOff[mt] + ks*32);
            }
            #pragma unroll
            for (int nt = 0; nt < 4; nt++) {
                ldm2(bh[nt], sB + bOff[nt] + ks*32);
                ldm2(bl[nt], sB + 10240 + bOff[nt] + ks*32);
            }
            #pragma unroll
            for (int mt = 0; mt < 3; mt++)
                #pragma unroll
                for (int nt = 0; nt < 4; nt++) {
                    mma_bf16(acc[mt][nt], ah[mt], bh[nt]);
                    mma_bf16(acc[mt][nt], ah[mt], bl[nt]);
                    mma_bf16(acc[mt][nt], al[mt], bh[nt]);
                }
        }
        __syncthreads();
    }

    int plane = (kz + 1) * 64;
    #pragma unroll
    for (int nt = 0; nt < 4; nt++) {
        int col = colBase + wn + nt*8 + (lane & 3)*2;
        int b = col >> 6, cc = col & 63;
        size_t boff = (size_t)b*192 + plane + cc;
        #pragma unroll
        for (int mt = 0; mt < 3; mt++) {
            int n0 = rowBase + wm + mt*16 + (lane >> 2);
            if (n0 < NN) {
                __nv_bfloat16 h0, l0, h1, l1;
                bf16_split(acc[mt][nt][0], h0, l0);
                bf16_split(acc[mt][nt][1], h1, l1);
                *(__nv_bfloat162*)(g_XGh + (size_t)n0*12288 + boff) = __halves2bfloat162(h0, h1);
                *(__nv_bfloat162*)(g_XGl + (size_t)n0*12288 + boff) = __halves2bfloat162(l0, l1);
            }
            if (n0 + 8 < NN) {
                __nv_bfloat16 h0, l0, h1, l1;
                bf16_split(acc[mt][nt][2], h0, l0);
                bf16_split(acc[mt][nt][3], h1, l1);
                *(__nv_bfloat162*)(g_XGh + (size_t)(n0+8)*12288 + boff) = __halves2bfloat162(h0, h1);
                *(__nv_bfloat162*)(g_XGl + (size_t)(n0+8)*12288 + boff) = __halves2bfloat162(l0, l1);
            }
        }
    }
}

// ---------------- K5: per-node [64,192]@[192,64] via mma.sync (R13 shape) ---
#define K5_AL 25600
#define K5_BH 51200
#define K5_BL 78848
__global__ void __launch_bounds__(256, 2) k5_mma() {
    extern __shared__ char smem[];
    uint32_t sb = smem_u32(smem);
    int t = threadIdx.x, w = t >> 5, lane = t & 31;
    int n = blockIdx.x;

    const __nv_bfloat16* Ah = g_XGh + (size_t)n*12288;
    const __nv_bfloat16* Al = g_XGl + (size_t)n*12288;
    const __nv_bfloat16* Bh = g_Wnh + (size_t)n*12288;
    const __nv_bfloat16* Bl = g_Wnl + (size_t)n*12288;

    for (int idx = t; idx < 1536; idx += 256) {       // A: 64 rows x 24 chunks
        int r = idx / 24, cc = idx - r*24;
        cp16(sb + r*400 + cc*16,          Ah + r*192 + cc*8);
        cp16(sb + K5_AL + r*400 + cc*16,  Al + r*192 + cc*8);
    }
    for (int idx = t; idx < 1536; idx += 256) {       // B: 192 rows x 8 chunks
        int r = idx >> 3, cc = idx & 7;
        cp16(sb + K5_BH + r*144 + cc*16,  Bh + r*64 + cc*8);
        cp16(sb + K5_BL + r*144 + cc*16,  Bl + r*64 + cc*8);
    }
    cp_commit();
    cp_wait0();
    __syncthreads();

    int wm = (w & 3) * 16, wn = (w >> 2) * 32;
    int g4 = lane >> 3;
    int rsel = (g4 & 1) * 8 + (lane & 7);
    int kselA = (g4 >> 1) * 8;
    uint32_t aAddrH = sb + (uint32_t)((wm + rsel)*400 + kselA*2);
    uint32_t aAddrL = aAddrH + K5_AL;
    uint32_t bRow = (uint32_t)(lane & 15);
    uint32_t bAddr[4];
    #pragma unroll
    for (int nt = 0; nt < 4; nt++)
        bAddr[nt] = sb + K5_BH + bRow*144 + (uint32_t)((wn + nt*8)*2);

    float acc[4][4];
    #pragma unroll
    for (int nt = 0; nt < 4; nt++)
        #pragma unroll
        for (int q = 0; q < 4; q++) acc[nt][q] = 0.f;

    #pragma unroll
    for (int kc = 0; kc < 12; kc++) {
        uint32_t ah[4], al[4];
        ldm4(ah, aAddrH + kc*32);
        ldm4(al, aAddrL + kc*32);
        #pragma unroll
        for (int nt = 0; nt < 4; nt++) {
            uint32_t bh[2], bl[2];
            ldm2t(bh, bAddr[nt] + (uint32_t)(kc*16*144));
            ldm2t(bl, bAddr[nt] + (uint32_t)(K5_BL - K5_BH) + (uint32_t)(kc*16*144));
            mma_bf16(acc[nt], ah, bh);
            mma_bf16(acc[nt], ah, bl);
            mma_bf16(acc[nt], al, bh);
        }
    }

    // epilogue: +bias, write H2 as single fp16
    #pragma unroll
    for (int nt = 0; nt < 4; nt++) {
        int o = wn + nt*8 + (lane & 3)*2;
        float2 bv = *(const float2*)(g_bn + n*64 + o);
        int b0 = wm + (lane >> 2);
        float v0 = acc[nt][0] + bv.x, v1 = acc[nt][1] + bv.y;
        float v2 = acc[nt][2] + bv.x, v3 = acc[nt][3] + bv.y;
        size_t r0 = ((size_t)(b0*NN + n))*64 + o;
        size_t r1 = ((size_t)((b0+8)*NN + n))*64 + o;
        *(__half2*)(g_H2f + r0) = __floats2half2_rn(v0, v1);
        *(__half2*)(g_H2f + r1) = __floats2half2_rn(v2, v3);
    }
}

// ---------------- K6: out = tanh(H2 @ W_out^T + b_out); fp16 2-term ---------
// A = H2 single fp16 (quant ~2^-12); B = W_out fp16 hi/lo split.
// D = A*Bh + A*Bl  -> 2/3 the MMA count of the 3-term bf16 scheme.
#define K6A   18432                    /* A: 128 rows x 144 B */
#define OFF_B 18432                    /* B: stage*36864 + split*18432 */
__global__ void __launch_bounds__(256, 2) k6_mma(const float* __restrict__ b_out,
                                                 float* __restrict__ out) {
    extern __shared__ char smem[];
    uint32_t sb = smem_u32(smem);
    int t = threadIdx.x, w = t >> 5, lane = t & 31;
    int rowBase = blockIdx.x * 128;
    int colSec  = blockIdx.y * 1024;
    int wm = (w & 1) * 64, wn = (w >> 1) * 32;

    // A: 128 rows x 8 chunks (single split)
    for (int idx = t; idx < 1024; idx += 256) {
        int r = idx >> 3, cb = idx & 7;
        cp16(sb + r*144 + cb*16, g_H2f + (size_t)(rowBase + r)*64 + cb*8);
    }
    // B stage 0
    for (int idx = t; idx < 2048; idx += 256) {
        int arr = idx >> 10, rem = idx & 1023;
        int r = rem >> 3, cb = rem & 7;
        const __half* src = (arr ? g_Wfl : g_Wfh) + (size_t)(colSec + r)*64 + cb*8;
        cp16(sb + OFF_B + arr*K6A + r*144 + cb*16, src);
    }
    cp_commit();
    cp_wait0();
    __syncthreads();

    int g4 = lane >> 3;
    int rsel = (g4 & 1) * 8 + (lane & 7);
    int kselA = (g4 >> 1) * 8;
    int nsel = lane & 7;
    int kselB = ((lane >> 3) & 1) * 8;

    uint32_t aBase[4];
    #pragma unroll
    for (int mt = 0; mt < 4; mt++)
        aBase[mt] = sb + (uint32_t)((wm + mt*16 + rsel)*144 + kselA*2);
    uint32_t bOff[4];
    #pragma unroll
    for (int nt = 0; nt < 4; nt++)
        bOff[nt] = (uint32_t)((wn + nt*8 + nsel)*144 + kselB*2);

    for (int it = 0; it < 8; it++) {
        int stage = it & 1;
        if (it + 1 < 8) {
            int nc = colSec + (it + 1) * 128;
            for (int idx = t; idx < 2048; idx += 256) {
                int arr = idx >> 10, rem = idx & 1023;
                int r = rem >> 3, cb = rem & 7;
                const __half* src = (arr ? g_Wfl : g_Wfh) + (size_t)(nc + r)*64 + cb*8;
                cp16(sb + OFF_B + (stage^1)*2*K6A + arr*K6A + r*144 + cb*16, src);
            }
        }
        cp_commit();

        float acc[4][4][4];
        #pragma unroll
        for (int mt = 0; mt < 4; mt++)
            #pragma unroll
            for (int nt = 0; nt < 4; nt++)
                #pragma unroll
                for (int q = 0; q < 4; q++) acc[mt][nt][q] = 0.f;

        uint32_t bStage = sb + OFF_B + stage*2*K6A;
        #pragma unroll
        for (int ks = 0; ks < 4; ks++) {
            uint32_t ah[4][4], bh[4][2], bl[4][2];
            #pragma unroll
            for (int mt = 0; mt < 4; mt++)
                ldm4(ah[mt], aBase[mt] + ks*32);
            #pragma unroll
            for (int nt = 0; nt < 4; nt++) {
                ldm2(bh[nt], bStage + bOff[nt] + ks*32);
                ldm2(bl[nt], bStage + K6A + bOff[nt] + ks*32);
            }
            #pragma unroll
            for (int mt = 0; mt < 4; mt++)
                #pragma unroll
                for (int nt = 0; nt < 4; nt++) {
                    mma_f16(acc[mt][nt], ah[mt], bh[nt]);
                    mma_f16(acc[mt][nt], ah[mt], bl[nt]);
                }
        }

        int colT = colSec + it*128 + wn;
        #pragma unroll
        for (int nt = 0; nt < 4; nt++) {
            int col = colT + nt*8 + (lane & 3)*2;
            float2 bv = *(const float2*)(b_out + col);
            #pragma unroll
            for (int mt = 0; mt < 4; mt++) {
                int row0 = rowBase + wm + mt*16 + (lane >> 2);
                float2 o0, o1;
                o0.x = my_tanh(acc[mt][nt][0] + bv.x);
                o0.y = my_tanh(acc[mt][nt][1] + bv.y);
                o1.x = my_tanh(acc[mt][nt][2] + bv.x);
                o1.y = my_tanh(acc[mt][nt][3] + bv.y);
                *(float2*)(out + (size_t)row0*HC2 + col)       = o0;
                *(float2*)(out + (size_t)(row0+8)*HC2 + col)   = o1;
            }
        }

        cp_wait0();
        __syncthreads();
    }
}

// ---------------- launch -----------------------------------------------------
extern "C" void kernel_launch(void* const* d_in, const int* in_sizes, int n_in,
                              void* d_out, int out_size) {
    const float* z      = (const float*)d_in[0];
    const float* W_in   = (const float*)d_in[1];
    const float* b_in   = (const float*)d_in[2];
    const float* W_out  = (const float*)d_in[3];
    const float* b_out  = (const float*)d_in[4];
    const float* emb    = (const float*)d_in[5];
    const float* wpool  = (const float*)d_in[6];
    const float* bpool  = (const float*)d_in[7];
    float* out = (float*)d_out;

    const int SM4 = 71680;        // A 2x15360 + B 2x20480
    const int SM5 = 106496;       // A 2x25600 + B 2x27648
    const int SM6 = 5 * K6A;      // A 18432 + B 4x18432 = 92160
    cudaFuncSetAttribute(k4_mma,
        cudaFuncAttributeMaxDynamicSharedMemorySize, SM4);
    cudaFuncSetAttribute(k5_mma,
        cudaFuncAttributeMaxDynamicSharedMemorySize, SM5);
    cudaFuncSetAttribute(k6_mma,
        cudaFuncAttributeMaxDynamicSharedMemorySize, SM6);

    L1_prologue<<<729, 320>>>(z, W_in, b_in, W_out, emb, wpool, bpool);
    L2_cheb_ht <<<364, 320>>>();
    k4_mma     <<<dim3(4, 32, 2), 256, SM4>>>();
    k5_mma     <<<NN, 256, SM5>>>();
    k6_mma     <<<dim3(150, 4), 256, SM6>>>(b_out, out);
}